// round 1
// baseline (speedup 1.0000x reference)
#include <cuda_runtime.h>
#include <math.h>

// Problem constants
#define B 4
#define C 3
#define NPTS 8192
#define KNN 20
#define OCH 64
#define EPS 1e-5
#define SLOPE 0.2f

// Device scratch (no allocations allowed)
__device__ int    g_idx[B * NPTS * KNN];
__device__ double g_stats[B * 27];
__device__ float  g_mean[B * OCH];
__device__ float  g_rstd[B * OCH];

// ---------------------------------------------------------------------------
// Kernel 0: zero the moment accumulators (must happen every call)
// ---------------------------------------------------------------------------
__global__ void k_init() {
    int t = threadIdx.x;
    if (t < B * 27) g_stats[t] = 0.0;
}

// ---------------------------------------------------------------------------
// Kernel 1: brute-force KNN, top-20 smallest squared distances per point.
// Each block = one chunk of 256 query points of one batch. All 8192 points
// of the batch staged in smem as float4{x,y,z,sq} (128 KB). All threads
// sweep j in lockstep -> LDS.128 broadcast.
// ---------------------------------------------------------------------------
__global__ void k_knn(const float* __restrict__ x) {
    extern __shared__ float4 s_pts[];
    const int b = blockIdx.y;
    const float* xb = x + b * C * NPTS;

    for (int j = threadIdx.x; j < NPTS; j += blockDim.x) {
        float a0 = xb[j];
        float a1 = xb[NPTS + j];
        float a2 = xb[2 * NPTS + j];
        s_pts[j] = make_float4(a0, a1, a2, a0 * a0 + a1 * a1 + a2 * a2);
    }
    __syncthreads();

    const int i = blockIdx.x * blockDim.x + threadIdx.x;
    const float4 pi = s_pts[i];

    float bd[KNN];
    int   bi[KNN];
#pragma unroll
    for (int k = 0; k < KNN; k++) { bd[k] = 3.4e38f; bi[k] = 0x7fffffff; }
    float worst = 3.4e38f;
    int worstSlot = 0, worstIdx = 0x7fffffff;

#pragma unroll 4
    for (int j = 0; j < NPTS; j++) {
        float4 p = s_pts[j];
        float dot = pi.x * p.x;
        dot = fmaf(pi.y, p.y, dot);
        dot = fmaf(pi.z, p.z, dot);
        float dist = fmaf(-2.0f, dot, pi.w + p.w);
        if (dist < worst) {   // strict <: on ties keep earlier (lower) index, matches jax top_k
            bd[worstSlot] = dist;
            bi[worstSlot] = j;
            // rescan for new worst; among equal values evict the larger index first
            float w = bd[0]; int wi = bi[0]; int ws = 0;
#pragma unroll
            for (int s = 1; s < KNN; s++) {
                bool gt = (bd[s] > w) || (bd[s] == w && bi[s] > wi);
                if (gt) { w = bd[s]; wi = bi[s]; ws = s; }
            }
            worst = w; worstIdx = wi; worstSlot = ws;
        }
    }
    (void)worstIdx;

    int* op = g_idx + (b * NPTS + i) * KNN;
#pragma unroll
    for (int k = 0; k < KNN; k++) op[k] = bi[k];
}

// ---------------------------------------------------------------------------
// Kernel 2: accumulate per-batch moments of the edge feature e = (xi, xj-xi):
// S1 = sum e (6), S2 = sum e e^T (sym 6x6 -> XX:6, XD:9, DD:6). 27 doubles/batch.
// ---------------------------------------------------------------------------
__global__ void k_stats(const float* __restrict__ x) {
    const int b = blockIdx.y;
    const int n = blockIdx.x * blockDim.x + threadIdx.x;
    const float* xb = x + b * C * NPTS;

    const float xi0 = xb[n], xi1 = xb[NPTS + n], xi2 = xb[2 * NPTS + n];
    const int* ip = g_idx + (b * NPTS + n) * KNN;

    float sd0 = 0.f, sd1 = 0.f, sd2 = 0.f;
    float s00 = 0.f, s01 = 0.f, s02 = 0.f, s11 = 0.f, s12 = 0.f, s22 = 0.f;
#pragma unroll
    for (int k = 0; k < KNN; k++) {
        int j = ip[k];
        float d0 = xb[j] - xi0;
        float d1 = xb[NPTS + j] - xi1;
        float d2 = xb[2 * NPTS + j] - xi2;
        sd0 += d0; sd1 += d1; sd2 += d2;
        s00 = fmaf(d0, d0, s00); s01 = fmaf(d0, d1, s01); s02 = fmaf(d0, d2, s02);
        s11 = fmaf(d1, d1, s11); s12 = fmaf(d1, d2, s12); s22 = fmaf(d2, d2, s22);
    }

    float v[27];
    v[0] = KNN * xi0; v[1] = KNN * xi1; v[2] = KNN * xi2;
    v[3] = sd0; v[4] = sd1; v[5] = sd2;
    v[6] = KNN * xi0 * xi0; v[7] = KNN * xi0 * xi1; v[8]  = KNN * xi0 * xi2;
    v[9] = KNN * xi1 * xi1; v[10] = KNN * xi1 * xi2; v[11] = KNN * xi2 * xi2;
    v[12] = xi0 * sd0; v[13] = xi0 * sd1; v[14] = xi0 * sd2;
    v[15] = xi1 * sd0; v[16] = xi1 * sd1; v[17] = xi1 * sd2;
    v[18] = xi2 * sd0; v[19] = xi2 * sd1; v[20] = xi2 * sd2;
    v[21] = s00; v[22] = s01; v[23] = s02; v[24] = s11; v[25] = s12; v[26] = s22;

    // warp reduce
#pragma unroll
    for (int q = 0; q < 27; q++) {
#pragma unroll
        for (int off = 16; off > 0; off >>= 1)
            v[q] += __shfl_down_sync(0xffffffffu, v[q], off);
    }

    __shared__ double sh[27];
    if (threadIdx.x < 27) sh[threadIdx.x] = 0.0;
    __syncthreads();
    if ((threadIdx.x & 31) == 0) {
#pragma unroll
        for (int q = 0; q < 27; q++) atomicAdd(&sh[q], (double)v[q]);
    }
    __syncthreads();
    if (threadIdx.x < 27) atomicAdd(&g_stats[b * 27 + threadIdx.x], sh[threadIdx.x]);
}

// ---------------------------------------------------------------------------
// Kernel 3: per-(b,o) mean / rstd from the quadratic form.  256 threads.
// ---------------------------------------------------------------------------
__global__ void k_norm(const float* __restrict__ W) {
    int t = threadIdx.x;
    int b = t / OCH, o = t % OCH;
    const float* w = W + o * 6;
    double wa0 = w[0], wa1 = w[1], wa2 = w[2];
    double wb0 = w[3], wb1 = w[4], wb2 = w[5];
    const double* G = g_stats + b * 27;
    const double NK = (double)NPTS * (double)KNN;

    double mean = (wa0 * G[0] + wa1 * G[1] + wa2 * G[2] +
                   wb0 * G[3] + wb1 * G[4] + wb2 * G[5]) / NK;

    double xx = wa0 * wa0 * G[6] + 2.0 * wa0 * wa1 * G[7] + 2.0 * wa0 * wa2 * G[8] +
                wa1 * wa1 * G[9] + 2.0 * wa1 * wa2 * G[10] + wa2 * wa2 * G[11];
    double xd = wa0 * (wb0 * G[12] + wb1 * G[13] + wb2 * G[14]) +
                wa1 * (wb0 * G[15] + wb1 * G[16] + wb2 * G[17]) +
                wa2 * (wb0 * G[18] + wb1 * G[19] + wb2 * G[20]);
    double dd = wb0 * wb0 * G[21] + 2.0 * wb0 * wb1 * G[22] + 2.0 * wb0 * wb2 * G[23] +
                wb1 * wb1 * G[24] + 2.0 * wb1 * wb2 * G[25] + wb2 * wb2 * G[26];

    double Ey2 = (xx + 2.0 * xd + dd) / NK;
    double var = Ey2 - mean * mean;
    g_mean[t] = (float)mean;
    g_rstd[t] = (float)(1.0 / sqrt(var + EPS));
}

// ---------------------------------------------------------------------------
// Kernel 4: conv + max over k (monotone: normalize+leaky applied after max).
// Thread = one point n; neighbor deltas cached in registers; loop over o.
// out layout [B, O, N] -> coalesced per-o across threads.
// ---------------------------------------------------------------------------
__global__ void k_out(const float* __restrict__ x, const float* __restrict__ W,
                      float* __restrict__ out) {
    const int b = blockIdx.y;
    const int n = blockIdx.x * blockDim.x + threadIdx.x;

    __shared__ float sW[OCH * 6];
    __shared__ float sM[OCH];
    __shared__ float sR[OCH];
    for (int t = threadIdx.x; t < OCH * 6; t += blockDim.x) sW[t] = W[t];
    if (threadIdx.x < OCH) {
        sM[threadIdx.x] = g_mean[b * OCH + threadIdx.x];
        sR[threadIdx.x] = g_rstd[b * OCH + threadIdx.x];
    }
    __syncthreads();

    const float* xb = x + b * C * NPTS;
    const float xi0 = xb[n], xi1 = xb[NPTS + n], xi2 = xb[2 * NPTS + n];
    const int* ip = g_idx + (b * NPTS + n) * KNN;

    float d0[KNN], d1[KNN], d2[KNN];
#pragma unroll
    for (int k = 0; k < KNN; k++) {
        int j = ip[k];
        d0[k] = xb[j] - xi0;
        d1[k] = xb[NPTS + j] - xi1;
        d2[k] = xb[2 * NPTS + j] - xi2;
    }

    float* ob = out + (size_t)b * OCH * NPTS + n;
    for (int o = 0; o < OCH; o++) {
        float wa0 = sW[o * 6 + 0], wa1 = sW[o * 6 + 1], wa2 = sW[o * 6 + 2];
        float wb0 = sW[o * 6 + 3], wb1 = sW[o * 6 + 4], wb2 = sW[o * 6 + 5];
        float p = wa0 * xi0;
        p = fmaf(wa1, xi1, p);
        p = fmaf(wa2, xi2, p);
        float m = -3.4e38f;
#pragma unroll
        for (int k = 0; k < KNN; k++) {
            float y = fmaf(wb2, d2[k], fmaf(wb1, d1[k], fmaf(wb0, d0[k], p)));
            m = fmaxf(m, y);
        }
        float z = (m - sM[o]) * sR[o];
        ob[(size_t)o * NPTS] = (z >= 0.f) ? z : SLOPE * z;
    }
}

// ---------------------------------------------------------------------------
extern "C" void kernel_launch(void* const* d_in, const int* in_sizes, int n_in,
                              void* d_out, int out_size) {
    const float* x = (const float*)d_in[0];   // [B, C, N]
    const float* W = (const float*)d_in[1];   // [O, 2C]
    float* out = (float*)d_out;               // [B, O, N]

    const int smem_knn = NPTS * sizeof(float4);   // 128 KB
    cudaFuncSetAttribute(k_knn, cudaFuncAttributeMaxDynamicSharedMemorySize, smem_knn);

    dim3 grid(NPTS / 256, B);

    k_init<<<1, 128>>>();
    k_knn<<<grid, 256, smem_knn>>>(x);
    k_stats<<<grid, 256>>>(x);
    k_norm<<<1, B * OCH>>>(W);
    k_out<<<grid, 256>>>(x, W, out);
}

// round 3
// speedup vs baseline: 1.9659x; 1.9659x over previous
#include <cuda_runtime.h>
#include <math.h>

// Problem constants
#define B 4
#define C 3
#define NPTS 8192
#define KNN 20
#define OCH 64
#define EPS 1e-5
#define SLOPE 0.2f

// Device scratch (no allocations allowed)
__device__ int    g_idx[B * NPTS * KNN];
__device__ double g_stats[B * 27];
__device__ float  g_mean[B * OCH];
__device__ float  g_rstd[B * OCH];

// ---------------------------------------------------------------------------
// Kernel 0: zero the moment accumulators (must happen every call)
// ---------------------------------------------------------------------------
__global__ void k_init() {
    int t = threadIdx.x;
    if (t < B * 27) g_stats[t] = 0.0;
}

// ---------------------------------------------------------------------------
// Register-resident insert into unordered top-KNN list. Static indexing only:
// predicated overwrite of the worst slot, then statically-unrolled rescan.
// Strict < keeps earlier index on boundary ties (matches jax top_k selection).
// ---------------------------------------------------------------------------
__device__ __forceinline__ void insert20(float (&bd)[KNN], int (&bi)[KNN],
                                         float& worst, int& wslot,
                                         float d, int j) {
    if (d < worst) {
#pragma unroll
        for (int s = 0; s < KNN; s++)
            if (s == wslot) { bd[s] = d; bi[s] = j; }
        float w = bd[0]; int ws = 0;
#pragma unroll
        for (int s = 1; s < KNN; s++)
            if (bd[s] > w) { w = bd[s]; ws = s; }
        worst = w; wslot = ws;
    }
}

// ---------------------------------------------------------------------------
// Kernel 1: brute-force KNN + fused moment accumulation.
// Block = 256 query points of one batch; all 8192 points of the batch staged
// in 128 KB smem as float4{x,y,z,sq}. Threads sweep j in lockstep (LDS.128
// broadcast). Candidates passing the (possibly stale) threshold go to an
// 8-deep register ring; the warp drains coherently when any lane has >= 4.
// ---------------------------------------------------------------------------
__global__ void k_knn(const float* __restrict__ x) {
    extern __shared__ float4 s_pts[];
    __shared__ double sh[27];

    const int b = blockIdx.y;
    const float* xb = x + b * C * NPTS;

    for (int j = threadIdx.x; j < NPTS; j += blockDim.x) {
        float a0 = xb[j];
        float a1 = xb[NPTS + j];
        float a2 = xb[2 * NPTS + j];
        s_pts[j] = make_float4(a0, a1, a2, fmaf(a0, a0, fmaf(a1, a1, a2 * a2)));
    }
    __syncthreads();

    const int i = blockIdx.x * blockDim.x + threadIdx.x;
    const float4 pi4 = s_pts[i];

    float bd[KNN];
    int   bi[KNN];
#pragma unroll
    for (int k = 0; k < KNN; k++) { bd[k] = 3.4e38f; bi[k] = 0; }
    float worst = 3.4e38f;
    int   wslot = 0;

    // 8-deep candidate buffer, all static indexing (predicated writes)
    float f0 = 0, f1 = 0, f2 = 0, f3 = 0, f4 = 0, f5 = 0, f6 = 0, f7 = 0;
    int   c0 = 0, c1 = 0, c2 = 0, c3 = 0, c4 = 0, c5 = 0, c6 = 0, c7 = 0;
    int   cnt = 0;

    auto drain = [&]() {
        if (cnt > 0) insert20(bd, bi, worst, wslot, f0, c0);
        if (cnt > 1) insert20(bd, bi, worst, wslot, f1, c1);
        if (cnt > 2) insert20(bd, bi, worst, wslot, f2, c2);
        if (cnt > 3) insert20(bd, bi, worst, wslot, f3, c3);
        if (cnt > 4) insert20(bd, bi, worst, wslot, f4, c4);
        if (cnt > 5) insert20(bd, bi, worst, wslot, f5, c5);
        if (cnt > 6) insert20(bd, bi, worst, wslot, f6, c6);
        if (cnt > 7) insert20(bd, bi, worst, wslot, f7, c7);
        cnt = 0;
    };

    for (int j0 = 0; j0 < NPTS; j0 += 4) {
#pragma unroll
        for (int u = 0; u < 4; u++) {
            const int j = j0 + u;
            float4 p = s_pts[j];
            float dot = pi4.x * p.x;
            dot = fmaf(pi4.y, p.y, dot);
            dot = fmaf(pi4.z, p.z, dot);
            float dist = fmaf(-2.0f, dot, pi4.w + p.w);
            if (dist < worst) {   // threshold may be stale -> superset, exact on drain
                f0 = (cnt == 0) ? dist : f0;  c0 = (cnt == 0) ? j : c0;
                f1 = (cnt == 1) ? dist : f1;  c1 = (cnt == 1) ? j : c1;
                f2 = (cnt == 2) ? dist : f2;  c2 = (cnt == 2) ? j : c2;
                f3 = (cnt == 3) ? dist : f3;  c3 = (cnt == 3) ? j : c3;
                f4 = (cnt == 4) ? dist : f4;  c4 = (cnt == 4) ? j : c4;
                f5 = (cnt == 5) ? dist : f5;  c5 = (cnt == 5) ? j : c5;
                f6 = (cnt == 6) ? dist : f6;  c6 = (cnt == 6) ? j : c6;
                f7 = (cnt == 7) ? dist : f7;  c7 = (cnt == 7) ? j : c7;
                cnt++;
            }
        }
        // checked every 4 j's: cnt can reach at most 3 + 4 = 7 < 8 before drain
        if (__any_sync(0xffffffffu, cnt >= 4)) drain();
    }
    drain();   // leftover candidates

    // write neighbor indices (order irrelevant: downstream is order-invariant)
    int* op = g_idx + (b * NPTS + i) * KNN;
#pragma unroll
    for (int k = 0; k < KNN; k++) op[k] = bi[k];

    // ---- fused moment accumulation (points still in smem) ----
    float sd0 = 0.f, sd1 = 0.f, sd2 = 0.f;
    float s00 = 0.f, s01 = 0.f, s02 = 0.f, s11 = 0.f, s12 = 0.f, s22 = 0.f;
#pragma unroll
    for (int k = 0; k < KNN; k++) {
        float4 p = s_pts[bi[k]];
        float d0 = p.x - pi4.x;
        float d1 = p.y - pi4.y;
        float d2 = p.z - pi4.z;
        sd0 += d0; sd1 += d1; sd2 += d2;
        s00 = fmaf(d0, d0, s00); s01 = fmaf(d0, d1, s01); s02 = fmaf(d0, d2, s02);
        s11 = fmaf(d1, d1, s11); s12 = fmaf(d1, d2, s12); s22 = fmaf(d2, d2, s22);
    }

    float v[27];
    v[0] = KNN * pi4.x; v[1] = KNN * pi4.y; v[2] = KNN * pi4.z;
    v[3] = sd0; v[4] = sd1; v[5] = sd2;
    v[6] = KNN * pi4.x * pi4.x; v[7] = KNN * pi4.x * pi4.y; v[8]  = KNN * pi4.x * pi4.z;
    v[9] = KNN * pi4.y * pi4.y; v[10] = KNN * pi4.y * pi4.z; v[11] = KNN * pi4.z * pi4.z;
    v[12] = pi4.x * sd0; v[13] = pi4.x * sd1; v[14] = pi4.x * sd2;
    v[15] = pi4.y * sd0; v[16] = pi4.y * sd1; v[17] = pi4.y * sd2;
    v[18] = pi4.z * sd0; v[19] = pi4.z * sd1; v[20] = pi4.z * sd2;
    v[21] = s00; v[22] = s01; v[23] = s02; v[24] = s11; v[25] = s12; v[26] = s22;

#pragma unroll
    for (int q = 0; q < 27; q++) {
#pragma unroll
        for (int off = 16; off > 0; off >>= 1)
            v[q] += __shfl_down_sync(0xffffffffu, v[q], off);
    }

    if (threadIdx.x < 27) sh[threadIdx.x] = 0.0;
    __syncthreads();
    if ((threadIdx.x & 31) == 0) {
#pragma unroll
        for (int q = 0; q < 27; q++) atomicAdd(&sh[q], (double)v[q]);
    }
    __syncthreads();
    if (threadIdx.x < 27) atomicAdd(&g_stats[b * 27 + threadIdx.x], sh[threadIdx.x]);
}

// ---------------------------------------------------------------------------
// Kernel 2: per-(b,o) mean / rstd from the quadratic form.  256 threads.
// ---------------------------------------------------------------------------
__global__ void k_norm(const float* __restrict__ W) {
    int t = threadIdx.x;
    int b = t / OCH, o = t % OCH;
    const float* w = W + o * 6;
    double wa0 = w[0], wa1 = w[1], wa2 = w[2];
    double wb0 = w[3], wb1 = w[4], wb2 = w[5];
    const double* G = g_stats + b * 27;
    const double NK = (double)NPTS * (double)KNN;

    double mean = (wa0 * G[0] + wa1 * G[1] + wa2 * G[2] +
                   wb0 * G[3] + wb1 * G[4] + wb2 * G[5]) / NK;

    double xx = wa0 * wa0 * G[6] + 2.0 * wa0 * wa1 * G[7] + 2.0 * wa0 * wa2 * G[8] +
                wa1 * wa1 * G[9] + 2.0 * wa1 * wa2 * G[10] + wa2 * wa2 * G[11];
    double xd = wa0 * (wb0 * G[12] + wb1 * G[13] + wb2 * G[14]) +
                wa1 * (wb0 * G[15] + wb1 * G[16] + wb2 * G[17]) +
                wa2 * (wb0 * G[18] + wb1 * G[19] + wb2 * G[20]);
    double dd = wb0 * wb0 * G[21] + 2.0 * wb0 * wb1 * G[22] + 2.0 * wb0 * wb2 * G[23] +
                wb1 * wb1 * G[24] + 2.0 * wb1 * wb2 * G[25] + wb2 * wb2 * G[26];

    double Ey2 = (xx + 2.0 * xd + dd) / NK;
    double var = Ey2 - mean * mean;
    g_mean[t] = (float)mean;
    g_rstd[t] = (float)(1.0 / sqrt(var + EPS));
}

// ---------------------------------------------------------------------------
// Kernel 3: conv + max over k (monotone: normalize+leaky applied after max).
// ---------------------------------------------------------------------------
__global__ void k_out(const float* __restrict__ x, const float* __restrict__ W,
                      float* __restrict__ out) {
    const int b = blockIdx.y;
    const int n = blockIdx.x * blockDim.x + threadIdx.x;

    __shared__ float sW[OCH * 6];
    __shared__ float sM[OCH];
    __shared__ float sR[OCH];
    for (int t = threadIdx.x; t < OCH * 6; t += blockDim.x) sW[t] = W[t];
    if (threadIdx.x < OCH) {
        sM[threadIdx.x] = g_mean[b * OCH + threadIdx.x];
        sR[threadIdx.x] = g_rstd[b * OCH + threadIdx.x];
    }
    __syncthreads();

    const float* xb = x + b * C * NPTS;
    const float xi0 = xb[n], xi1 = xb[NPTS + n], xi2 = xb[2 * NPTS + n];
    const int* ip = g_idx + (b * NPTS + n) * KNN;

    float d0[KNN], d1[KNN], d2[KNN];
#pragma unroll
    for (int k = 0; k < KNN; k++) {
        int j = ip[k];
        d0[k] = xb[j] - xi0;
        d1[k] = xb[NPTS + j] - xi1;
        d2[k] = xb[2 * NPTS + j] - xi2;
    }

    float* ob = out + (size_t)b * OCH * NPTS + n;
    for (int o = 0; o < OCH; o++) {
        float wa0 = sW[o * 6 + 0], wa1 = sW[o * 6 + 1], wa2 = sW[o * 6 + 2];
        float wb0 = sW[o * 6 + 3], wb1 = sW[o * 6 + 4], wb2 = sW[o * 6 + 5];
        float p = wa0 * xi0;
        p = fmaf(wa1, xi1, p);
        p = fmaf(wa2, xi2, p);
        float m = -3.4e38f;
#pragma unroll
        for (int k = 0; k < KNN; k++) {
            float y = fmaf(wb2, d2[k], fmaf(wb1, d1[k], fmaf(wb0, d0[k], p)));
            m = fmaxf(m, y);
        }
        float z = (m - sM[o]) * sR[o];
        ob[(size_t)o * NPTS] = (z >= 0.f) ? z : SLOPE * z;
    }
}

// ---------------------------------------------------------------------------
extern "C" void kernel_launch(void* const* d_in, const int* in_sizes, int n_in,
                              void* d_out, int out_size) {
    const float* x = (const float*)d_in[0];   // [B, C, N]
    const float* W = (const float*)d_in[1];   // [O, 2C]
    float* out = (float*)d_out;               // [B, O, N]

    const int smem_knn = NPTS * sizeof(float4);   // 128 KB
    cudaFuncSetAttribute(k_knn, cudaFuncAttributeMaxDynamicSharedMemorySize, smem_knn);

    dim3 grid(NPTS / 256, B);

    k_init<<<1, 128>>>();
    k_knn<<<grid, 256, smem_knn>>>(x);
    k_norm<<<1, B * OCH>>>(W);
    k_out<<<grid, 256>>>(x, W, out);
}

// round 4
// speedup vs baseline: 2.9213x; 1.4860x over previous
#include <cuda_runtime.h>
#include <math.h>

// Problem constants
#define B 4
#define C 3
#define NPTS 8192
#define KNN 20
#define OCH 64
#define EPS 1e-5
#define SLOPE 0.2f

// Device scratch (no allocations allowed)
__device__ int    g_idx[B * NPTS * KNN];
__device__ double g_stats[B * 27];
__device__ float  g_mean[B * OCH];
__device__ float  g_rstd[B * OCH];

// ---------------------------------------------------------------------------
// Kernel 0: zero the moment accumulators (must happen every call)
// ---------------------------------------------------------------------------
__global__ void k_init() {
    int t = threadIdx.x;
    if (t < B * 27) g_stats[t] = 0.0;
}

// ---------------------------------------------------------------------------
// Branchless predicated insert into unordered top-KNN register list.
// Static indexing only (SELs). Rescan is idempotent, so it is safe to execute
// even for lanes that did not insert. Eviction tie-break: among equal-worst
// distances evict the LARGER index, so the lower index is kept (matches jax
// top_k boundary semantics). Insertion uses strict <, and j arrives in
// ascending order, so an incoming tie at the boundary is correctly rejected.
// ---------------------------------------------------------------------------
__device__ __forceinline__ void insert20_pred(float (&bd)[KNN], int (&bi)[KNN],
                                              float& worst, int& wslot, int& widx,
                                              float d, int j, bool en) {
    bool ins = en && (d < worst);
#pragma unroll
    for (int s = 0; s < KNN; s++) {
        bool hit = ins && (s == wslot);
        bd[s] = hit ? d : bd[s];
        bi[s] = hit ? j : bi[s];
    }
    float w = bd[0]; int wi = bi[0]; int ws = 0;
#pragma unroll
    for (int s = 1; s < KNN; s++) {
        bool gt = (bd[s] > w) || (bd[s] == w && bi[s] > wi);
        w  = gt ? bd[s] : w;
        wi = gt ? bi[s] : wi;
        ws = gt ? s : ws;
    }
    worst = w; wslot = ws; widx = wi;
}

// ---------------------------------------------------------------------------
// Kernel 1: brute-force KNN + fused moment accumulation.
// Block = 256 query points of one batch; all 8192 points staged in 128 KB
// smem as float4{x,y,z,sq}; j swept in lockstep (LDS.128 broadcast).
// ALL branches in the hot loop are warp-uniform (__any_sync results) — no
// divergent BSSY/BSYNC. Candidate pushes and drain inserts are branchless
// predicated SELs.
// ---------------------------------------------------------------------------
__global__ void k_knn(const float* __restrict__ x) {
    extern __shared__ float4 s_pts[];
    __shared__ double sh[27];

    const int b = blockIdx.y;
    const float* xb = x + b * C * NPTS;

    for (int j = threadIdx.x; j < NPTS; j += blockDim.x) {
        float a0 = xb[j];
        float a1 = xb[NPTS + j];
        float a2 = xb[2 * NPTS + j];
        s_pts[j] = make_float4(a0, a1, a2, fmaf(a0, a0, fmaf(a1, a1, a2 * a2)));
    }
    __syncthreads();

    const int i = blockIdx.x * blockDim.x + threadIdx.x;
    const float4 pi4 = s_pts[i];

    float bd[KNN];
    int   bi[KNN];
#pragma unroll
    for (int k = 0; k < KNN; k++) { bd[k] = 3.4e38f; bi[k] = 0; }
    float worst = 3.4e38f;
    int   wslot = 0, widx = 0;

    // 8-deep candidate buffer, static indexing (predicated SEL writes)
    float f0 = 0, f1 = 0, f2 = 0, f3 = 0, f4 = 0, f5 = 0, f6 = 0, f7 = 0;
    int   c0 = 0, c1 = 0, c2 = 0, c3 = 0, c4 = 0, c5 = 0, c6 = 0, c7 = 0;
    int   cnt = 0;

#define PUSH(dv, jv, tv) do {                                              \
        bool q0 = (tv) && cnt == 0; f0 = q0 ? (dv) : f0; c0 = q0 ? (jv) : c0; \
        bool q1 = (tv) && cnt == 1; f1 = q1 ? (dv) : f1; c1 = q1 ? (jv) : c1; \
        bool q2 = (tv) && cnt == 2; f2 = q2 ? (dv) : f2; c2 = q2 ? (jv) : c2; \
        bool q3 = (tv) && cnt == 3; f3 = q3 ? (dv) : f3; c3 = q3 ? (jv) : c3; \
        bool q4 = (tv) && cnt == 4; f4 = q4 ? (dv) : f4; c4 = q4 ? (jv) : c4; \
        bool q5 = (tv) && cnt == 5; f5 = q5 ? (dv) : f5; c5 = q5 ? (jv) : c5; \
        bool q6 = (tv) && cnt == 6; f6 = q6 ? (dv) : f6; c6 = q6 ? (jv) : c6; \
        bool q7 = (tv) && cnt == 7; f7 = q7 ? (dv) : f7; c7 = q7 ? (jv) : c7; \
        cnt += (tv) ? 1 : 0;                                               \
    } while (0)

#define DRAIN_STEP(s, fv, cv)                                                \
    if (__any_sync(0xffffffffu, cnt > (s) && (fv) < worst))                  \
        insert20_pred(bd, bi, worst, wslot, widx, fv, cv, cnt > (s));

#define DRAIN() do {                    \
        DRAIN_STEP(0, f0, c0)           \
        DRAIN_STEP(1, f1, c1)           \
        DRAIN_STEP(2, f2, c2)           \
        DRAIN_STEP(3, f3, c3)           \
        DRAIN_STEP(4, f4, c4)           \
        DRAIN_STEP(5, f5, c5)           \
        DRAIN_STEP(6, f6, c6)           \
        DRAIN_STEP(7, f7, c7)           \
        cnt = 0;                        \
    } while (0)

    for (int j0 = 0; j0 < NPTS; j0 += 4) {
        float4 p0 = s_pts[j0 + 0];
        float4 p1 = s_pts[j0 + 1];
        float4 p2 = s_pts[j0 + 2];
        float4 p3 = s_pts[j0 + 3];
        float dA = fmaf(-2.0f, fmaf(pi4.z, p0.z, fmaf(pi4.y, p0.y, pi4.x * p0.x)), pi4.w + p0.w);
        float dB = fmaf(-2.0f, fmaf(pi4.z, p1.z, fmaf(pi4.y, p1.y, pi4.x * p1.x)), pi4.w + p1.w);
        float dC = fmaf(-2.0f, fmaf(pi4.z, p2.z, fmaf(pi4.y, p2.y, pi4.x * p2.x)), pi4.w + p2.w);
        float dD = fmaf(-2.0f, fmaf(pi4.z, p3.z, fmaf(pi4.y, p3.y, pi4.x * p3.x)), pi4.w + p3.w);
        bool t0 = dA < worst, t1 = dB < worst, t2 = dC < worst, t3 = dD < worst;
        if (__any_sync(0xffffffffu, t0 | t1 | t2 | t3)) {     // uniform branch
            PUSH(dA, j0 + 0, t0);
            PUSH(dB, j0 + 1, t1);
            PUSH(dC, j0 + 2, t2);
            PUSH(dD, j0 + 3, t3);
            // cnt was <= 3 on entry (post-drain invariant), so <= 7 here
            if (__any_sync(0xffffffffu, cnt >= 4)) DRAIN();   // uniform branch
        }
    }
    DRAIN();   // leftovers

#undef PUSH
#undef DRAIN_STEP
#undef DRAIN

    // write neighbor indices (order irrelevant: downstream is order-invariant)
    int* op = g_idx + (b * NPTS + i) * KNN;
#pragma unroll
    for (int k = 0; k < KNN; k++) op[k] = bi[k];

    // ---- fused moment accumulation (points still in smem) ----
    float sd0 = 0.f, sd1 = 0.f, sd2 = 0.f;
    float s00 = 0.f, s01 = 0.f, s02 = 0.f, s11 = 0.f, s12 = 0.f, s22 = 0.f;
#pragma unroll
    for (int k = 0; k < KNN; k++) {
        float4 p = s_pts[bi[k]];
        float d0 = p.x - pi4.x;
        float d1 = p.y - pi4.y;
        float d2 = p.z - pi4.z;
        sd0 += d0; sd1 += d1; sd2 += d2;
        s00 = fmaf(d0, d0, s00); s01 = fmaf(d0, d1, s01); s02 = fmaf(d0, d2, s02);
        s11 = fmaf(d1, d1, s11); s12 = fmaf(d1, d2, s12); s22 = fmaf(d2, d2, s22);
    }

    float v[27];
    v[0] = KNN * pi4.x; v[1] = KNN * pi4.y; v[2] = KNN * pi4.z;
    v[3] = sd0; v[4] = sd1; v[5] = sd2;
    v[6] = KNN * pi4.x * pi4.x; v[7] = KNN * pi4.x * pi4.y; v[8]  = KNN * pi4.x * pi4.z;
    v[9] = KNN * pi4.y * pi4.y; v[10] = KNN * pi4.y * pi4.z; v[11] = KNN * pi4.z * pi4.z;
    v[12] = pi4.x * sd0; v[13] = pi4.x * sd1; v[14] = pi4.x * sd2;
    v[15] = pi4.y * sd0; v[16] = pi4.y * sd1; v[17] = pi4.y * sd2;
    v[18] = pi4.z * sd0; v[19] = pi4.z * sd1; v[20] = pi4.z * sd2;
    v[21] = s00; v[22] = s01; v[23] = s02; v[24] = s11; v[25] = s12; v[26] = s22;

#pragma unroll
    for (int q = 0; q < 27; q++) {
#pragma unroll
        for (int off = 16; off > 0; off >>= 1)
            v[q] += __shfl_down_sync(0xffffffffu, v[q], off);
    }

    if (threadIdx.x < 27) sh[threadIdx.x] = 0.0;
    __syncthreads();
    if ((threadIdx.x & 31) == 0) {
#pragma unroll
        for (int q = 0; q < 27; q++) atomicAdd(&sh[q], (double)v[q]);
    }
    __syncthreads();
    if (threadIdx.x < 27) atomicAdd(&g_stats[b * 27 + threadIdx.x], sh[threadIdx.x]);
}

// ---------------------------------------------------------------------------
// Kernel 2: per-(b,o) mean / rstd from the quadratic form.  256 threads.
// ---------------------------------------------------------------------------
__global__ void k_norm(const float* __restrict__ W) {
    int t = threadIdx.x;
    int b = t / OCH, o = t % OCH;
    const float* w = W + o * 6;
    double wa0 = w[0], wa1 = w[1], wa2 = w[2];
    double wb0 = w[3], wb1 = w[4], wb2 = w[5];
    const double* G = g_stats + b * 27;
    const double NK = (double)NPTS * (double)KNN;

    double mean = (wa0 * G[0] + wa1 * G[1] + wa2 * G[2] +
                   wb0 * G[3] + wb1 * G[4] + wb2 * G[5]) / NK;

    double xx = wa0 * wa0 * G[6] + 2.0 * wa0 * wa1 * G[7] + 2.0 * wa0 * wa2 * G[8] +
                wa1 * wa1 * G[9] + 2.0 * wa1 * wa2 * G[10] + wa2 * wa2 * G[11];
    double xd = wa0 * (wb0 * G[12] + wb1 * G[13] + wb2 * G[14]) +
                wa1 * (wb0 * G[15] + wb1 * G[16] + wb2 * G[17]) +
                wa2 * (wb0 * G[18] + wb1 * G[19] + wb2 * G[20]);
    double dd = wb0 * wb0 * G[21] + 2.0 * wb0 * wb1 * G[22] + 2.0 * wb0 * wb2 * G[23] +
                wb1 * wb1 * G[24] + 2.0 * wb1 * wb2 * G[25] + wb2 * wb2 * G[26];

    double Ey2 = (xx + 2.0 * xd + dd) / NK;
    double var = Ey2 - mean * mean;
    g_mean[t] = (float)mean;
    g_rstd[t] = (float)(1.0 / sqrt(var + EPS));
}

// ---------------------------------------------------------------------------
// Kernel 3: conv + max over k (monotone: normalize+leaky applied after max).
// ---------------------------------------------------------------------------
__global__ void k_out(const float* __restrict__ x, const float* __restrict__ W,
                      float* __restrict__ out) {
    const int b = blockIdx.y;
    const int n = blockIdx.x * blockDim.x + threadIdx.x;

    __shared__ float sW[OCH * 6];
    __shared__ float sM[OCH];
    __shared__ float sR[OCH];
    for (int t = threadIdx.x; t < OCH * 6; t += blockDim.x) sW[t] = W[t];
    if (threadIdx.x < OCH) {
        sM[threadIdx.x] = g_mean[b * OCH + threadIdx.x];
        sR[threadIdx.x] = g_rstd[b * OCH + threadIdx.x];
    }
    __syncthreads();

    const float* xb = x + b * C * NPTS;
    const float xi0 = xb[n], xi1 = xb[NPTS + n], xi2 = xb[2 * NPTS + n];
    const int* ip = g_idx + (b * NPTS + n) * KNN;

    float d0[KNN], d1[KNN], d2[KNN];
#pragma unroll
    for (int k = 0; k < KNN; k++) {
        int j = ip[k];
        d0[k] = xb[j] - xi0;
        d1[k] = xb[NPTS + j] - xi1;
        d2[k] = xb[2 * NPTS + j] - xi2;
    }

    float* ob = out + (size_t)b * OCH * NPTS + n;
    for (int o = 0; o < OCH; o++) {
        float wa0 = sW[o * 6 + 0], wa1 = sW[o * 6 + 1], wa2 = sW[o * 6 + 2];
        float wb0 = sW[o * 6 + 3], wb1 = sW[o * 6 + 4], wb2 = sW[o * 6 + 5];
        float p = wa0 * xi0;
        p = fmaf(wa1, xi1, p);
        p = fmaf(wa2, xi2, p);
        float m = -3.4e38f;
#pragma unroll
        for (int k = 0; k < KNN; k++) {
            float y = fmaf(wb2, d2[k], fmaf(wb1, d1[k], fmaf(wb0, d0[k], p)));
            m = fmaxf(m, y);
        }
        float z = (m - sM[o]) * sR[o];
        ob[(size_t)o * NPTS] = (z >= 0.f) ? z : SLOPE * z;
    }
}

// ---------------------------------------------------------------------------
extern "C" void kernel_launch(void* const* d_in, const int* in_sizes, int n_in,
                              void* d_out, int out_size) {
    const float* x = (const float*)d_in[0];   // [B, C, N]
    const float* W = (const float*)d_in[1];   // [O, 2C]
    float* out = (float*)d_out;               // [B, O, N]

    const int smem_knn = NPTS * sizeof(float4);   // 128 KB
    cudaFuncSetAttribute(k_knn, cudaFuncAttributeMaxDynamicSharedMemorySize, smem_knn);

    dim3 grid(NPTS / 256, B);

    k_init<<<1, 128>>>();
    k_knn<<<grid, 256, smem_knn>>>(x);
    k_norm<<<1, B * OCH>>>(W);
    k_out<<<grid, 256>>>(x, W, out);
}